// round 12
// baseline (speedup 1.0000x reference)
#include <cuda_runtime.h>
#include <cuda_bf16.h>
#include <math.h>
#include <stdint.h>

// Problem constants (fixed by the reference setup)
#define BB   8
#define TT   1024
#define TEE  1024
#define HH   1024
#define NHH  8
#define DKK  128
#define MM   (BB * TT)       // 8192 rows
#define FF   4096            // FFN hidden

// ---------------------------------------------------------------------------
// Scratch (static device globals)
// ---------------------------------------------------------------------------
__device__ float ws_q  [MM * HH];
__device__ float ws_k  [MM * HH];
__device__ float ws_v  [MM * HH];
__device__ float ws_x  [MM * HH];
__device__ float ws_z  [MM * HH];
__device__ float ws_a  [MM * HH];    // tf32-rounded A operand (LN out / ctx / enc)
__device__ float ws_hid[MM * FF];    // tf32-rounded FFN hidden
__device__ float ws_b  [FF * HH];    // tf32-rounded weight operand

// ---------------------------------------------------------------------------
// tf32 rna rounding helper
// ---------------------------------------------------------------------------
__device__ __forceinline__ float rna_tf32(float x) {
    uint32_t u;
    asm("cvt.rna.tf32.f32 %0, %1;" : "=r"(u) : "f"(x));
    return __uint_as_float(u);
}

// standalone round: 4 floats/thread; n % 1024 == 0
__global__ __launch_bounds__(256)
void round_kernel(const float* __restrict__ x, float* __restrict__ y)
{
    const long long i = (long long)blockIdx.x * 256 + threadIdx.x;
    float4 v = ((const float4*)x)[i];
    v.x = rna_tf32(v.x); v.y = rna_tf32(v.y);
    v.z = rna_tf32(v.z); v.w = rna_tf32(v.w);
    ((float4*)y)[i] = v;
}

// ---------------------------------------------------------------------------
// MMA / ldmatrix / cp.async primitives
// ---------------------------------------------------------------------------
__device__ __forceinline__ void mma_tf32(float* c, const uint32_t* a, const uint32_t* b) {
    asm volatile(
        "mma.sync.aligned.m16n8k8.row.col.f32.tf32.tf32.f32 "
        "{%0,%1,%2,%3},{%4,%5,%6,%7},{%8,%9},{%0,%1,%2,%3};"
        : "+f"(c[0]), "+f"(c[1]), "+f"(c[2]), "+f"(c[3])
        : "r"(a[0]), "r"(a[1]), "r"(a[2]), "r"(a[3]), "r"(b[0]), "r"(b[1]));
}

__device__ __forceinline__ void ldm_x4(uint32_t addr, uint32_t* r) {
    asm volatile("ldmatrix.sync.aligned.m8n8.x4.shared.b16 {%0,%1,%2,%3}, [%4];"
        : "=r"(r[0]), "=r"(r[1]), "=r"(r[2]), "=r"(r[3]) : "r"(addr));
}

__device__ __forceinline__ void cp_async16(uint32_t smem_addr, const void* gptr) {
    asm volatile("cp.async.cg.shared.global [%0], [%1], 16;"
                 :: "r"(smem_addr), "l"(gptr));
}

// ---------------------------------------------------------------------------
// tf32 tensor-core GEMM, 3-stage cp.async pipeline:
//   C = A[M,K] @ B[N,K]^T  (+ bias/relu/resid), operands tf32-pre-rounded.
// CTA tile 128x128, 8 warps (2x4), warp tile 64x32, K-chunk 32.
// smem 3 x (A plane + B plane) = 110,592 B; 2 CTAs/SM.
// ---------------------------------------------------------------------------
#define SROWF 36
#define PLANEF (128 * SROWF)
#define BUFF (2 * PLANEF)
#define GEMM_SMEM (3 * BUFF * 4)         // 110592 B

__global__ __launch_bounds__(256, 2)
void gemm_tf32_kernel(const float* __restrict__ A,
                      const float* __restrict__ B,
                      float* __restrict__ C,
                      int ldc, int M, int N, int K,
                      const float* __restrict__ bias,
                      const float* __restrict__ resid, int ldres,
                      int relu, int round_out)
{
    extern __shared__ float smf[];

    const int tid  = threadIdx.x;
    const int warp = tid >> 5;
    const int lane = tid & 31;
    const int wm = warp >> 2;
    const int wn = warp & 3;
    const int qr = lane >> 2;
    const int qc = lane & 3;
    const int m0 = blockIdx.y * 128;
    const int n0 = blockIdx.x * 128;

    const uint32_t sbase = (uint32_t)__cvta_generic_to_shared(smf);

    const int aRow = ((lane >> 3) & 1) * 8 + (lane & 7);
    const int aKof = (lane >> 4) * 4;
    const int bRow = (lane >> 4) * 8 + (lane & 7);
    const int bKof = ((lane >> 3) & 1) * 4;

    float acc[4][4][4];
    #pragma unroll
    for (int mt = 0; mt < 4; ++mt)
        #pragma unroll
        for (int nt = 0; nt < 4; ++nt)
            #pragma unroll
            for (int r = 0; r < 4; ++r) acc[mt][nt][r] = 0.f;

    auto issue = [&](int buf, int kk0) {
        #pragma unroll
        for (int i = 0; i < 8; ++i) {
            const int op   = i >> 2;
            const int widx = (i & 3) * 256 + tid;
            const int row  = widx >> 3;
            const int g    = widx & 7;
            const float* src = op
                ? B + (long long)(n0 + row) * K + kk0 + g * 4
                : A + (long long)(m0 + row) * K + kk0 + g * 4;
            const uint32_t soff = (uint32_t)((buf * BUFF + op * PLANEF + row * SROWF + g * 4) * 4);
            cp_async16(sbase + soff, src);
        }
        asm volatile("cp.async.commit_group;");
    };

    const int nchunks = K >> 5;

    // prologue: two chunks in flight
    issue(0, 0);
    if (nchunks > 1) issue(1, 32);
    asm volatile("cp.async.wait_group 1;");   // chunk 0 ready (chunk 1 may fly)
    __syncthreads();

    for (int t = 0; t < nchunks; ++t) {
        const int buf = t % 3;
        // issue chunk t+2 into buf (t+2)%3 == (t-1)%3, whose readers finished
        // before the sync at the end of iteration t-1.
        if (t + 2 < nchunks) issue((t + 2) % 3, (t + 2) * 32);

        const uint32_t bufF = (uint32_t)(buf * BUFF);

        #pragma unroll
        for (int ks = 0; ks < 4; ++ks) {
            const int k0 = ks * 8;
            uint32_t bf[2][4];
            #pragma unroll
            for (int p = 0; p < 2; ++p) {
                const uint32_t off = sbase +
                    (uint32_t)((bufF + PLANEF + (wn * 32 + p * 16 + bRow) * SROWF + k0 + bKof) * 4);
                ldm_x4(off, bf[p]);
            }
            #pragma unroll
            for (int mt = 0; mt < 4; ++mt) {
                uint32_t af[4];
                const uint32_t off = sbase +
                    (uint32_t)((bufF + (wm * 64 + mt * 16 + aRow) * SROWF + k0 + aKof) * 4);
                ldm_x4(off, af);
                #pragma unroll
                for (int nt = 0; nt < 4; ++nt) {
                    const uint32_t* bb = &bf[nt >> 1][(nt & 1) * 2];
                    mma_tf32(acc[mt][nt], af, bb);
                }
            }
        }

        if (t + 1 < nchunks) {
            asm volatile("cp.async.wait_group 1;");   // chunk t+1 ready
            __syncthreads();
        }
    }

    #pragma unroll
    for (int mt = 0; mt < 4; ++mt) {
        const int row0 = m0 + wm * 64 + mt * 16 + qr;
        #pragma unroll
        for (int nt = 0; nt < 4; ++nt) {
            const int col = n0 + wn * 32 + nt * 8 + qc * 2;
            float2 v0 = make_float2(acc[mt][nt][0], acc[mt][nt][1]);
            float2 v1 = make_float2(acc[mt][nt][2], acc[mt][nt][3]);
            if (bias) {
                float2 b2 = *(const float2*)(bias + col);
                v0.x += b2.x; v0.y += b2.y;
                v1.x += b2.x; v1.y += b2.y;
            }
            if (relu) {
                v0.x = fmaxf(v0.x, 0.f); v0.y = fmaxf(v0.y, 0.f);
                v1.x = fmaxf(v1.x, 0.f); v1.y = fmaxf(v1.y, 0.f);
            }
            if (resid) {
                float2 r0 = *(const float2*)(resid + (long long)row0 * ldres + col);
                float2 r1 = *(const float2*)(resid + (long long)(row0 + 8) * ldres + col);
                v0.x += r0.x; v0.y += r0.y;
                v1.x += r1.x; v1.y += r1.y;
            }
            if (round_out) {
                v0.x = rna_tf32(v0.x); v0.y = rna_tf32(v0.y);
                v1.x = rna_tf32(v1.x); v1.y = rna_tf32(v1.y);
            }
            *(float2*)(C + (long long)row0 * ldc + col)       = v0;
            *(float2*)(C + (long long)(row0 + 8) * ldc + col) = v1;
        }
    }
}

// ---------------------------------------------------------------------------
// Tensor-core flash attention (tf32, DK=128) — unchanged from R11 (validated).
// ---------------------------------------------------------------------------
#define FBQ 128
#define FBK 32
#define QSTR 132
#define VSTR 36
#define SVT_OFF (FBK * QSTR)             // 4224 floats
#define SP_OFF  (SVT_OFF + 128 * VSTR)   // 8832 floats
#define FLASH_SMEM (FBQ * QSTR * 4)      // 67584 B

__global__ __launch_bounds__(256)
void flash_tc_kernel(const float* __restrict__ Qg, const float* __restrict__ Kg,
                     const float* __restrict__ Vg, float* __restrict__ Og,
                     int Tk, int causal)
{
    extern __shared__ float sm[];
    float* sQ  = sm;
    float* sK  = sm;                 // reuses sQ region after prologue
    float* sVt = sm + SVT_OFF;

    const int tid  = threadIdx.x;
    const int warp = tid >> 5;
    const int lane = tid & 31;
    const int qr = lane >> 2, qc = lane & 3;
    const int q0 = blockIdx.x * FBQ;
    const int bh = blockIdx.y;
    const int bb = bh >> 3, hh = bh & 7;

    const float* Qp = Qg + ((long long)(bb * TT + q0)) * HH + hh * DKK;
    const float* Kp = Kg + ((long long)bb * Tk) * HH + hh * DKK;
    const float* Vp = Vg + ((long long)bb * Tk) * HH + hh * DKK;

    const uint32_t sbase = (uint32_t)__cvta_generic_to_shared(sm);

    const int aRow = ((lane >> 3) & 1) * 8 + (lane & 7);
    const int aKof = (lane >> 4) * 4;
    const int bRow = (lane >> 4) * 8 + (lane & 7);
    const int bKof = ((lane >> 3) & 1) * 4;

    // ---- prologue: Q tile -> smem -> register fragments ----
    #pragma unroll
    for (int i = 0; i < 16; ++i) {
        int idx = i * 256 + tid;
        int row = idx >> 5, c4 = (idx & 31) * 4;
        *(float4*)&sQ[row * QSTR + c4] = *(const float4*)(Qp + (long long)row * HH + c4);
    }
    __syncthreads();
    uint32_t qf[16][4];
    {
        const int rb = warp * 16 + aRow;
        #pragma unroll
        for (int ks = 0; ks < 16; ++ks)
            ldm_x4(sbase + (uint32_t)((rb * QSTR + ks * 8 + aKof) * 4), qf[ks]);
    }
    __syncthreads();

    const float scale = 0.08838834764831845f;
    float o[16][4];
    #pragma unroll
    for (int nt = 0; nt < 16; ++nt) {
        o[nt][0] = 0.f; o[nt][1] = 0.f; o[nt][2] = 0.f; o[nt][3] = 0.f;
    }
    float m0 = -INFINITY, m1 = -INFINITY, l0 = 0.f, l1 = 0.f;

    const int nkt = causal ? (q0 / FBK + 4) : (Tk / FBK);

    for (int kt = 0; kt < nkt; ++kt) {
        #pragma unroll
        for (int i = 0; i < 4; ++i) {
            int idx = i * 256 + tid;
            int row = idx >> 5, c4 = (idx & 31) * 4;
            *(float4*)&sK[row * QSTR + c4] =
                *(const float4*)(Kp + (long long)(kt * FBK + row) * HH + c4);
        }
        #pragma unroll
        for (int i = 0; i < 4; ++i) {
            int db = i * 8 + warp;
            float4 v4 = *(const float4*)(Vp + (long long)(kt * FBK + lane) * HH + db * 4);
            sVt[(db * 4 + 0) * VSTR + lane] = v4.x;
            sVt[(db * 4 + 1) * VSTR + lane] = v4.y;
            sVt[(db * 4 + 2) * VSTR + lane] = v4.z;
            sVt[(db * 4 + 3) * VSTR + lane] = v4.w;
        }
        __syncthreads();

        float facc[4][4];
        #pragma unroll
        for (int nt = 0; nt < 4; ++nt) {
            facc[nt][0] = 0.f; facc[nt][1] = 0.f; facc[nt][2] = 0.f; facc[nt][3] = 0.f;
        }
        #pragma unroll
        for (int ks = 0; ks < 16; ++ks) {
            uint32_t bf[2][4];
            #pragma unroll
            for (int p = 0; p < 2; ++p)
                ldm_x4(sbase + (uint32_t)(((p * 16 + bRow) * QSTR + ks * 8 + bKof) * 4), bf[p]);
            #pragma unroll
            for (int nt = 0; nt < 4; ++nt)
                mma_tf32(facc[nt], qf[ks], &bf[nt >> 1][(nt & 1) * 2]);
        }

        const int gq0 = q0 + warp * 16 + qr;
        const int gq1 = gq0 + 8;
        float mx0 = -INFINITY, mx1 = -INFINITY;
        #pragma unroll
        for (int nt = 0; nt < 4; ++nt) {
            const int kc0 = kt * FBK + nt * 8 + 2 * qc;
            facc[nt][0] *= scale; facc[nt][1] *= scale;
            facc[nt][2] *= scale; facc[nt][3] *= scale;
            if (causal) {
                if (kc0     > gq0) facc[nt][0] = -INFINITY;
                if (kc0 + 1 > gq0) facc[nt][1] = -INFINITY;
                if (kc0     > gq1) facc[nt][2] = -INFINITY;
                if (kc0 + 1 > gq1) facc[nt][3] = -INFINITY;
            }
            mx0 = fmaxf(mx0, fmaxf(facc[nt][0], facc[nt][1]));
            mx1 = fmaxf(mx1, fmaxf(facc[nt][2], facc[nt][3]));
        }
        mx0 = fmaxf(mx0, __shfl_xor_sync(0xffffffffu, mx0, 1));
        mx0 = fmaxf(mx0, __shfl_xor_sync(0xffffffffu, mx0, 2));
        mx1 = fmaxf(mx1, __shfl_xor_sync(0xffffffffu, mx1, 1));
        mx1 = fmaxf(mx1, __shfl_xor_sync(0xffffffffu, mx1, 2));
        const float mn0 = fmaxf(m0, mx0), mn1 = fmaxf(m1, mx1);
        const float corr0 = __expf(m0 - mn0), corr1 = __expf(m1 - mn1);

        float rs0 = 0.f, rs1 = 0.f;
        #pragma unroll
        for (int nt = 0; nt < 4; ++nt) {
            float p0 = __expf(facc[nt][0] - mn0), p1 = __expf(facc[nt][1] - mn0);
            float p2 = __expf(facc[nt][2] - mn1), p3 = __expf(facc[nt][3] - mn1);
            rs0 += p0 + p1; rs1 += p2 + p3;
            *(float2*)&sm[SP_OFF + (warp * 16 + qr) * VSTR + nt * 8 + 2 * qc] =
                make_float2(rna_tf32(p0), rna_tf32(p1));
            *(float2*)&sm[SP_OFF + (warp * 16 + qr + 8) * VSTR + nt * 8 + 2 * qc] =
                make_float2(rna_tf32(p2), rna_tf32(p3));
        }
        rs0 += __shfl_xor_sync(0xffffffffu, rs0, 1);
        rs0 += __shfl_xor_sync(0xffffffffu, rs0, 2);
        rs1 += __shfl_xor_sync(0xffffffffu, rs1, 1);
        rs1 += __shfl_xor_sync(0xffffffffu, rs1, 2);
        l0 = l0 * corr0 + rs0;  l1 = l1 * corr1 + rs1;
        m0 = mn0;  m1 = mn1;
        #pragma unroll
        for (int nt = 0; nt < 16; ++nt) {
            o[nt][0] *= corr0; o[nt][1] *= corr0;
            o[nt][2] *= corr1; o[nt][3] *= corr1;
        }
        __syncwarp();

        #pragma unroll
        for (int ks = 0; ks < 4; ++ks) {
            uint32_t af[4];
            ldm_x4(sbase + (uint32_t)((SP_OFF + (warp * 16 + aRow) * VSTR + ks * 8 + aKof) * 4), af);
            #pragma unroll
            for (int p = 0; p < 8; ++p) {
                uint32_t bf[4];
                ldm_x4(sbase + (uint32_t)((SVT_OFF + (p * 16 + bRow) * VSTR + ks * 8 + bKof) * 4), bf);
                mma_tf32(o[p * 2],     af, &bf[0]);
                mma_tf32(o[p * 2 + 1], af, &bf[2]);
            }
        }
        __syncthreads();
    }

    const float inv0 = 1.f / l0, inv1 = 1.f / l1;
    const long long r0 = ((long long)(bb * TT + q0 + warp * 16 + qr)) * HH + hh * DKK;
    const long long r1 = r0 + 8LL * HH;
    #pragma unroll
    for (int nt = 0; nt < 16; ++nt) {
        const int d = nt * 8 + 2 * qc;
        *(float2*)(Og + r0 + d) =
            make_float2(rna_tf32(o[nt][0] * inv0), rna_tf32(o[nt][1] * inv0));
        *(float2*)(Og + r1 + d) =
            make_float2(rna_tf32(o[nt][2] * inv1), rna_tf32(o[nt][3] * inv1));
    }
}

// ---------------------------------------------------------------------------
// LayerNorm over last dim (1024); writes tf32-rounded fp32 directly.
// ---------------------------------------------------------------------------
__global__ __launch_bounds__(256)
void layernorm_round_kernel(const float* __restrict__ x, const float* __restrict__ g,
                            const float* __restrict__ b, float* __restrict__ y)
{
    const long long row = blockIdx.x;
    const int tid = threadIdx.x;
    float4 v = ((const float4*)(x + row * HH))[tid];

    __shared__ float red[8];
    float s = v.x + v.y + v.z + v.w;
    #pragma unroll
    for (int o = 16; o; o >>= 1) s += __shfl_xor_sync(0xffffffffu, s, o);
    if ((tid & 31) == 0) red[tid >> 5] = s;
    __syncthreads();
    float mean = (red[0] + red[1] + red[2] + red[3] +
                  red[4] + red[5] + red[6] + red[7]) * (1.f / HH);
    __syncthreads();

    float dx = v.x - mean, dy = v.y - mean, dz = v.z - mean, dw = v.w - mean;
    float sq = dx * dx + dy * dy + dz * dz + dw * dw;
    #pragma unroll
    for (int o = 16; o; o >>= 1) sq += __shfl_xor_sync(0xffffffffu, sq, o);
    if ((tid & 31) == 0) red[tid >> 5] = sq;
    __syncthreads();
    float var = (red[0] + red[1] + red[2] + red[3] +
                 red[4] + red[5] + red[6] + red[7]) * (1.f / HH);
    float rstd = rsqrtf(var + 1e-5f);

    float4 g4 = ((const float4*)g)[tid];
    float4 b4 = ((const float4*)b)[tid];
    float4 o4;
    o4.x = rna_tf32(dx * rstd * g4.x + b4.x);
    o4.y = rna_tf32(dy * rstd * g4.y + b4.y);
    o4.z = rna_tf32(dz * rstd * g4.z + b4.z);
    o4.w = rna_tf32(dw * rstd * g4.w + b4.w);
    ((float4*)(y + row * HH))[tid] = o4;
}

// ---------------------------------------------------------------------------
// Host orchestration
// ---------------------------------------------------------------------------
extern "C" void kernel_launch(void* const* d_in, const int* in_sizes, int n_in,
                              void* d_out, int out_size)
{
    const float* input_ = (const float*)d_in[0];
    const float* enc    = (const float*)d_in[1];
    const float* Wq_s = (const float*)d_in[4];
    const float* Wk_s = (const float*)d_in[5];
    const float* Wv_s = (const float*)d_in[6];
    const float* Wo_s = (const float*)d_in[7];
    const float* Wq_c = (const float*)d_in[8];
    const float* Wk_c = (const float*)d_in[9];
    const float* Wv_c = (const float*)d_in[10];
    const float* Wo_c = (const float*)d_in[11];
    const float* w1   = (const float*)d_in[12];
    const float* b1   = (const float*)d_in[13];
    const float* w2   = (const float*)d_in[14];
    const float* b2   = (const float*)d_in[15];
    const float* g_mmha = (const float*)d_in[16];
    const float* b_mmha = (const float*)d_in[17];
    const float* g_mha  = (const float*)d_in[18];
    const float* b_mha  = (const float*)d_in[19];
    const float* g_ffn  = (const float*)d_in[20];
    const float* b_ffn  = (const float*)d_in[21];
    float* out = (float*)d_out;

    float *q, *k, *v, *x, *z, *a, *hid, *bw;
    cudaGetSymbolAddress((void**)&q,   ws_q);
    cudaGetSymbolAddress((void**)&k,   ws_k);
    cudaGetSymbolAddress((void**)&v,   ws_v);
    cudaGetSymbolAddress((void**)&x,   ws_x);
    cudaGetSymbolAddress((void**)&z,   ws_z);
    cudaGetSymbolAddress((void**)&a,   ws_a);
    cudaGetSymbolAddress((void**)&hid, ws_hid);
    cudaGetSymbolAddress((void**)&bw,  ws_b);

    cudaFuncSetAttribute(flash_tc_kernel,
                         cudaFuncAttributeMaxDynamicSharedMemorySize, FLASH_SMEM);
    cudaFuncSetAttribute(gemm_tf32_kernel,
                         cudaFuncAttributeMaxDynamicSharedMemorySize, GEMM_SMEM);

    auto roundw = [&](const float* src, float* dst, long long n) {
        round_kernel<<<(int)(n / 1024), 256>>>(src, dst);
    };
    auto gemm = [&](const float* pA, float* C, int M, int N, int K,
                    const float* bias, const float* resid, int relu, int round_out) {
        dim3 grid(N / 128, M / 128, 1);
        gemm_tf32_kernel<<<grid, 256, GEMM_SMEM>>>(pA, bw, C, N, M, N, K,
                                                   bias, resid, N, relu, round_out);
    };
    auto flash = [&](const float* Q, const float* K, const float* V, float* O,
                     int Tk, int causal) {
        dim3 grid(TT / FBQ, BB * NHH);
        flash_tc_kernel<<<grid, 256, FLASH_SMEM>>>(Q, K, V, O, Tk, causal);
    };

    const long long nW  = (long long)HH * HH;
    const long long nW1 = (long long)FF * HH;
    const long long nMH = (long long)MM * HH;

    // ---- self attention ----
    layernorm_round_kernel<<<MM, 256>>>(input_, g_mmha, b_mmha, a);
    roundw(Wq_s, bw, nW);  gemm(a, q, MM, HH, HH, nullptr, nullptr, 0, 1);
    roundw(Wk_s, bw, nW);  gemm(a, k, MM, HH, HH, nullptr, nullptr, 0, 1);
    roundw(Wv_s, bw, nW);  gemm(a, v, MM, HH, HH, nullptr, nullptr, 0, 1);
    flash(q, k, v, a, TT, /*causal=*/1);                 // ctx (rounded) -> a
    roundw(Wo_s, bw, nW);  gemm(a, x, MM, HH, HH, nullptr, input_, 0, 0);

    // ---- cross attention ----
    layernorm_round_kernel<<<MM, 256>>>(x, g_mha, b_mha, a);
    roundw(Wq_c, bw, nW);  gemm(a, q, MM, HH, HH, nullptr, nullptr, 0, 1);
    roundw(enc, a, nMH);                                 // enc (rounded) -> a
    roundw(Wk_c, bw, nW);  gemm(a, k, BB * TEE, HH, HH, nullptr, nullptr, 0, 1);
    roundw(Wv_c, bw, nW);  gemm(a, v, BB * TEE, HH, HH, nullptr, nullptr, 0, 1);
    flash(q, k, v, a, TEE, /*causal=*/0);
    roundw(Wo_c, bw, nW);  gemm(a, z, MM, HH, HH, nullptr, x, 0, 0);

    // ---- FFN ----
    layernorm_round_kernel<<<MM, 256>>>(z, g_ffn, b_ffn, a);
    roundw(w1, bw, nW1);   gemm(a, hid, MM, FF, HH, b1, nullptr, 1, 1);
    roundw(w2, bw, nW1);   gemm(hid, out, MM, HH, FF, b2, z, 0, 0);
}

// round 15
// speedup vs baseline: 1.3845x; 1.3845x over previous
#include <cuda_runtime.h>
#include <cuda_fp16.h>
#include <cuda_bf16.h>
#include <math.h>
#include <stdint.h>

// Problem constants (fixed by the reference setup)
#define BB   8
#define TT   1024
#define TEE  1024
#define HH   1024
#define NHH  8
#define DKK  128
#define MM   (BB * TT)       // 8192 rows
#define FF   4096            // FFN hidden

// ---------------------------------------------------------------------------
// Scratch (static device globals)
// ---------------------------------------------------------------------------
__device__ float ws_q  [MM * HH];
__device__ float ws_k  [MM * HH];
__device__ float ws_v  [MM * HH];
__device__ float ws_x  [MM * HH];
__device__ float ws_z  [MM * HH];
__device__ __half ws_a  [MM * HH];   // fp16 A operand (LN out / ctx / enc)
__device__ __half ws_hid[MM * FF];   // fp16 FFN hidden
__device__ __half ws_b  [FF * HH];   // fp16 weight operand

// ---------------------------------------------------------------------------
// Rounding helpers
// ---------------------------------------------------------------------------
__device__ __forceinline__ float rna_tf32(float x) {
    uint32_t u;
    asm("cvt.rna.tf32.f32 %0, %1;" : "=r"(u) : "f"(x));
    return __uint_as_float(u);
}

// fp32 -> fp16 convert kernel: 4 floats/thread; n % 1024 == 0
__global__ __launch_bounds__(256)
void tohalf_kernel(const float* __restrict__ x, __half* __restrict__ y)
{
    const long long i = (long long)blockIdx.x * 256 + threadIdx.x;
    float4 v = ((const float4*)x)[i];
    __half2* o = (__half2*)(y + i * 4);
    o[0] = __floats2half2_rn(v.x, v.y);
    o[1] = __floats2half2_rn(v.z, v.w);
}

// ---------------------------------------------------------------------------
// MMA / ldmatrix / cp.async primitives
// ---------------------------------------------------------------------------
__device__ __forceinline__ void mma_f16(float* c, const uint32_t* a, const uint32_t* b) {
    asm volatile(
        "mma.sync.aligned.m16n8k16.row.col.f32.f16.f16.f32 "
        "{%0,%1,%2,%3},{%4,%5,%6,%7},{%8,%9},{%0,%1,%2,%3};"
        : "+f"(c[0]), "+f"(c[1]), "+f"(c[2]), "+f"(c[3])
        : "r"(a[0]), "r"(a[1]), "r"(a[2]), "r"(a[3]), "r"(b[0]), "r"(b[1]));
}

__device__ __forceinline__ void mma_tf32(float* c, const uint32_t* a, const uint32_t* b) {
    asm volatile(
        "mma.sync.aligned.m16n8k8.row.col.f32.tf32.tf32.f32 "
        "{%0,%1,%2,%3},{%4,%5,%6,%7},{%8,%9},{%0,%1,%2,%3};"
        : "+f"(c[0]), "+f"(c[1]), "+f"(c[2]), "+f"(c[3])
        : "r"(a[0]), "r"(a[1]), "r"(a[2]), "r"(a[3]), "r"(b[0]), "r"(b[1]));
}

__device__ __forceinline__ void ldm_x4(uint32_t addr, uint32_t* r) {
    asm volatile("ldmatrix.sync.aligned.m8n8.x4.shared.b16 {%0,%1,%2,%3}, [%4];"
        : "=r"(r[0]), "=r"(r[1]), "=r"(r[2]), "=r"(r[3]) : "r"(addr));
}

__device__ __forceinline__ void cp_async16(uint32_t smem_addr, const void* gptr) {
    asm volatile("cp.async.cg.shared.global [%0], [%1], 16;"
                 :: "r"(smem_addr), "l"(gptr));
}

// ---------------------------------------------------------------------------
// fp16 tensor-core GEMM:  C = A[M,K] @ B[N,K]^T  (+ bias/relu/resid)
// Single-term fp16 (10-bit mantissa == tf32), m16n8k16: HALF the MMA count
// of the tf32 path for the same delivered precision (anchors: bf16/8b->2e-3,
// tf32/10b->2.5e-4 measured).
// CTA tile 128x128, 8 warps (2x4), warp tile 64x32, K-chunk 32, 2-stage
// cp.async; ldmatrix.x4 fragments (SROWH=40 halves -> conflict-free, layout
// numerically validated in the R8 bf16 kernel).
// Output: fp32 C (optionally rna-tf32 rounded) or fp16 Ch.
// Requires: M,N % 128 == 0, K % 32 == 0.
// ---------------------------------------------------------------------------
#define SROWH 40                           // halves per smem row (32 data + 8 pad)
#define PLANEH (128 * SROWH)               // 5120 halves
#define BUFH (2 * PLANEH)                  // A plane + B plane
#define GEMM_SMEM (2 * BUFH * 2)           // 40960 B

__global__ __launch_bounds__(256, 2)
void gemm_fp16_kernel(const __half* __restrict__ A,
                      const __half* __restrict__ B,
                      float* __restrict__ C,
                      __half* __restrict__ Ch,
                      int ldc, int M, int N, int K,
                      const float* __restrict__ bias,
                      const float* __restrict__ resid, int ldres,
                      int relu, int round_out)
{
    extern __shared__ __half smh[];

    const int tid  = threadIdx.x;
    const int warp = tid >> 5;
    const int lane = tid & 31;
    const int wm = warp >> 2;
    const int wn = warp & 3;
    const int qr = lane >> 2;
    const int qc = lane & 3;
    const int m0 = blockIdx.y * 128;
    const int n0 = blockIdx.x * 128;

    const uint32_t sbase = (uint32_t)__cvta_generic_to_shared(smh);

    // b16 ldmatrix addressing (validated R8)
    const int aRow = lane & 15;
    const int aKof = (lane >> 4) * 8;
    const int bRow = (lane >> 4) * 8 + (lane & 7);
    const int bKof = ((lane >> 3) & 1) * 8;

    float acc[4][4][4];
    #pragma unroll
    for (int mt = 0; mt < 4; ++mt)
        #pragma unroll
        for (int nt = 0; nt < 4; ++nt)
            #pragma unroll
            for (int r = 0; r < 4; ++r) acc[mt][nt][r] = 0.f;

    // copy: per plane 128 rows x 4 granules (16B = 8 halves); 1024 total, 4/thread
    auto issue = [&](int buf, int kk0) {
        #pragma unroll
        for (int i = 0; i < 4; ++i) {
            const int op   = i >> 1;                 // 0=A, 1=B
            const int widx = (i & 1) * 256 + tid;    // 0..511
            const int row  = widx >> 2;
            const int g    = widx & 3;
            const __half* src = op
                ? B + (long long)(n0 + row) * K + kk0 + g * 8
                : A + (long long)(m0 + row) * K + kk0 + g * 8;
            const uint32_t soff = (uint32_t)((buf * BUFH + op * PLANEH + row * SROWH + g * 8) * 2);
            cp_async16(sbase + soff, src);
        }
        asm volatile("cp.async.commit_group;");
    };

    const int nchunks = K >> 5;

    issue(0, 0);
    asm volatile("cp.async.wait_group 0;");
    __syncthreads();

    for (int t = 0; t < nchunks; ++t) {
        const int buf = t & 1;
        if (t + 1 < nchunks) issue(buf ^ 1, (t + 1) * 32);

        const uint32_t bufH = (uint32_t)(buf * BUFH);

        #pragma unroll
        for (int ks = 0; ks < 2; ++ks) {
            const int k0 = ks * 16;
            uint32_t bf[2][4];
            #pragma unroll
            for (int p = 0; p < 2; ++p) {
                const uint32_t off = sbase +
                    (uint32_t)((bufH + PLANEH + (wn * 32 + p * 16 + bRow) * SROWH + k0 + bKof) * 2);
                ldm_x4(off, bf[p]);
            }
            #pragma unroll
            for (int mt = 0; mt < 4; ++mt) {
                uint32_t af[4];
                const uint32_t off = sbase +
                    (uint32_t)((bufH + (wm * 64 + mt * 16 + aRow) * SROWH + k0 + aKof) * 2);
                ldm_x4(off, af);
                #pragma unroll
                for (int nt = 0; nt < 4; ++nt)
                    mma_f16(acc[mt][nt], af, &bf[nt >> 1][(nt & 1) * 2]);
            }
        }

        if (t + 1 < nchunks) {
            asm volatile("cp.async.wait_group 0;");
            __syncthreads();
        }
    }

    // Epilogue: frag -> rows qr,+8 ; cols 2*qc,+1.
    #pragma unroll
    for (int mt = 0; mt < 4; ++mt) {
        const int row0 = m0 + wm * 64 + mt * 16 + qr;
        #pragma unroll
        for (int nt = 0; nt < 4; ++nt) {
            const int col = n0 + wn * 32 + nt * 8 + qc * 2;
            float2 v0 = make_float2(acc[mt][nt][0], acc[mt][nt][1]);
            float2 v1 = make_float2(acc[mt][nt][2], acc[mt][nt][3]);
            if (bias) {
                float2 b2 = *(const float2*)(bias + col);
                v0.x += b2.x; v0.y += b2.y;
                v1.x += b2.x; v1.y += b2.y;
            }
            if (relu) {
                v0.x = fmaxf(v0.x, 0.f); v0.y = fmaxf(v0.y, 0.f);
                v1.x = fmaxf(v1.x, 0.f); v1.y = fmaxf(v1.y, 0.f);
            }
            if (resid) {
                float2 r0 = *(const float2*)(resid + (long long)row0 * ldres + col);
                float2 r1 = *(const float2*)(resid + (long long)(row0 + 8) * ldres + col);
                v0.x += r0.x; v0.y += r0.y;
                v1.x += r1.x; v1.y += r1.y;
            }
            if (Ch) {
                *(__half2*)(Ch + (long long)row0 * ldc + col)       = __floats2half2_rn(v0.x, v0.y);
                *(__half2*)(Ch + (long long)(row0 + 8) * ldc + col) = __floats2half2_rn(v1.x, v1.y);
            } else {
                if (round_out) {
                    v0.x = rna_tf32(v0.x); v0.y = rna_tf32(v0.y);
                    v1.x = rna_tf32(v1.x); v1.y = rna_tf32(v1.y);
                }
                *(float2*)(C + (long long)row0 * ldc + col)       = v0;
                *(float2*)(C + (long long)(row0 + 8) * ldc + col) = v1;
            }
        }
    }
}

// ---------------------------------------------------------------------------
// Tensor-core flash attention (tf32, DK=128) — validated R11; epilogue now
// writes fp16 ctx (feeds the fp16 Wo GEMM).
// ---------------------------------------------------------------------------
#define FBQ 128
#define FBK 32
#define QSTR 132
#define VSTR 36
#define SVT_OFF (FBK * QSTR)
#define SP_OFF  (SVT_OFF + 128 * VSTR)
#define FLASH_SMEM (FBQ * QSTR * 4)

__global__ __launch_bounds__(256)
void flash_tc_kernel(const float* __restrict__ Qg, const float* __restrict__ Kg,
                     const float* __restrict__ Vg, __half* __restrict__ Og,
                     int Tk, int causal)
{
    extern __shared__ float sm[];
    float* sQ  = sm;
    float* sK  = sm;
    float* sVt = sm + SVT_OFF;

    const int tid  = threadIdx.x;
    const int warp = tid >> 5;
    const int lane = tid & 31;
    const int qr = lane >> 2, qc = lane & 3;
    const int q0 = blockIdx.x * FBQ;
    const int bh = blockIdx.y;
    const int bb = bh >> 3, hh = bh & 7;

    const float* Qp = Qg + ((long long)(bb * TT + q0)) * HH + hh * DKK;
    const float* Kp = Kg + ((long long)bb * Tk) * HH + hh * DKK;
    const float* Vp = Vg + ((long long)bb * Tk) * HH + hh * DKK;

    const uint32_t sbase = (uint32_t)__cvta_generic_to_shared(sm);

    const int aRow = ((lane >> 3) & 1) * 8 + (lane & 7);
    const int aKof = (lane >> 4) * 4;
    const int bRow = (lane >> 4) * 8 + (lane & 7);
    const int bKof = ((lane >> 3) & 1) * 4;

    #pragma unroll
    for (int i = 0; i < 16; ++i) {
        int idx = i * 256 + tid;
        int row = idx >> 5, c4 = (idx & 31) * 4;
        *(float4*)&sQ[row * QSTR + c4] = *(const float4*)(Qp + (long long)row * HH + c4);
    }
    __syncthreads();
    uint32_t qf[16][4];
    {
        const int rb = warp * 16 + aRow;
        #pragma unroll
        for (int ks = 0; ks < 16; ++ks)
            ldm_x4(sbase + (uint32_t)((rb * QSTR + ks * 8 + aKof) * 4), qf[ks]);
    }
    __syncthreads();

    const float scale = 0.08838834764831845f;
    float o[16][4];
    #pragma unroll
    for (int nt = 0; nt < 16; ++nt) {
        o[nt][0] = 0.f; o[nt][1] = 0.f; o[nt][2] = 0.f; o[nt][3] = 0.f;
    }
    float m0 = -INFINITY, m1 = -INFINITY, l0 = 0.f, l1 = 0.f;

    const int nkt = causal ? (q0 / FBK + 4) : (Tk / FBK);

    for (int kt = 0; kt < nkt; ++kt) {
        #pragma unroll
        for (int i = 0; i < 4; ++i) {
            int idx = i * 256 + tid;
            int row = idx >> 5, c4 = (idx & 31) * 4;
            *(float4*)&sK[row * QSTR + c4] =
                *(const float4*)(Kp + (long long)(kt * FBK + row) * HH + c4);
        }
        #pragma unroll
        for (int i = 0; i < 4; ++i) {
            int db = i * 8 + warp;
            float4 v4 = *(const float4*)(Vp + (long long)(kt * FBK + lane) * HH + db * 4);
            sVt[(db * 4 + 0) * VSTR + lane] = v4.x;
            sVt[(db * 4 + 1) * VSTR + lane] = v4.y;
            sVt[(db * 4 + 2) * VSTR + lane] = v4.z;
            sVt[(db * 4 + 3) * VSTR + lane] = v4.w;
        }
        __syncthreads();

        float facc[4][4];
        #pragma unroll
        for (int nt = 0; nt < 4; ++nt) {
            facc[nt][0] = 0.f; facc[nt][1] = 0.f; facc[nt][2] = 0.f; facc[nt][3] = 0.f;
        }
        #pragma unroll
        for (int ks = 0; ks < 16; ++ks) {
            uint32_t bf[2][4];
            #pragma unroll
            for (int p = 0; p < 2; ++p)
                ldm_x4(sbase + (uint32_t)(((p * 16 + bRow) * QSTR + ks * 8 + bKof) * 4), bf[p]);
            #pragma unroll
            for (int nt = 0; nt < 4; ++nt)
                mma_tf32(facc[nt], qf[ks], &bf[nt >> 1][(nt & 1) * 2]);
        }

        const int gq0 = q0 + warp * 16 + qr;
        const int gq1 = gq0 + 8;
        float mx0 = -INFINITY, mx1 = -INFINITY;
        #pragma unroll
        for (int nt = 0; nt < 4; ++nt) {
            const int kc0 = kt * FBK + nt * 8 + 2 * qc;
            facc[nt][0] *= scale; facc[nt][1] *= scale;
            facc[nt][2] *= scale; facc[nt][3] *= scale;
            if (causal) {
                if (kc0     > gq0) facc[nt][0] = -INFINITY;
                if (kc0 + 1 > gq0) facc[nt][1] = -INFINITY;
                if (kc0     > gq1) facc[nt][2] = -INFINITY;
                if (kc0 + 1 > gq1) facc[nt][3] = -INFINITY;
            }
            mx0 = fmaxf(mx0, fmaxf(facc[nt][0], facc[nt][1]));
            mx1 = fmaxf(mx1, fmaxf(facc[nt][2], facc[nt][3]));
        }
        mx0 = fmaxf(mx0, __shfl_xor_sync(0xffffffffu, mx0, 1));
        mx0 = fmaxf(mx0, __shfl_xor_sync(0xffffffffu, mx0, 2));
        mx1 = fmaxf(mx1, __shfl_xor_sync(0xffffffffu, mx1, 1));
        mx1 = fmaxf(mx1, __shfl_xor_sync(0xffffffffu, mx1, 2));
        const float mn0 = fmaxf(m0, mx0), mn1 = fmaxf(m1, mx1);
        const float corr0 = __expf(m0 - mn0), corr1 = __expf(m1 - mn1);

        float rs0 = 0.f, rs1 = 0.f;
        #pragma unroll
        for (int nt = 0; nt < 4; ++nt) {
            float p0 = __expf(facc[nt][0] - mn0), p1 = __expf(facc[nt][1] - mn0);
            float p2 = __expf(facc[nt][2] - mn1), p3 = __expf(facc[nt][3] - mn1);
            rs0 += p0 + p1; rs1 += p2 + p3;
            *(float2*)&sm[SP_OFF + (warp * 16 + qr) * VSTR + nt * 8 + 2 * qc] =
                make_float2(rna_tf32(p0), rna_tf32(p1));
            *(float2*)&sm[SP_OFF + (warp * 16 + qr + 8) * VSTR + nt * 8 + 2 * qc] =
                make_float2(rna_tf32(p2), rna_tf32(p3));
        }
        rs0 += __shfl_xor_sync(0xffffffffu, rs0, 1);
        rs0 += __shfl_xor_sync(0xffffffffu, rs0, 2);
        rs1 += __shfl_xor_sync(0xffffffffu, rs1, 1);
        rs1 += __shfl_xor_sync(0xffffffffu, rs1, 2);
        l0 = l0 * corr0 + rs0;  l1 = l1 * corr1 + rs1;
        m0 = mn0;  m1 = mn1;
        #pragma unroll
        for (int nt = 0; nt < 16; ++nt) {
            o[nt][0] *= corr0; o[nt][1] *= corr0;
            o[nt][2] *= corr1; o[nt][3] *= corr1;
        }
        __syncwarp();

        #pragma unroll
        for (int ks = 0; ks < 4; ++ks) {
            uint32_t af[4];
            ldm_x4(sbase + (uint32_t)((SP_OFF + (warp * 16 + aRow) * VSTR + ks * 8 + aKof) * 4), af);
            #pragma unroll
            for (int p = 0; p < 8; ++p) {
                uint32_t bf[4];
                ldm_x4(sbase + (uint32_t)((SVT_OFF + (p * 16 + bRow) * VSTR + ks * 8 + bKof) * 4), bf);
                mma_tf32(o[p * 2],     af, &bf[0]);
                mma_tf32(o[p * 2 + 1], af, &bf[2]);
            }
        }
        __syncthreads();
    }

    const float inv0 = 1.f / l0, inv1 = 1.f / l1;
    const long long r0 = ((long long)(bb * TT + q0 + warp * 16 + qr)) * HH + hh * DKK;
    const long long r1 = r0 + 8LL * HH;
    #pragma unroll
    for (int nt = 0; nt < 16; ++nt) {
        const int d = nt * 8 + 2 * qc;
        *(__half2*)(Og + r0 + d) = __floats2half2_rn(o[nt][0] * inv0, o[nt][1] * inv0);
        *(__half2*)(Og + r1 + d) = __floats2half2_rn(o[nt][2] * inv1, o[nt][3] * inv1);
    }
}

// ---------------------------------------------------------------------------
// LayerNorm over last dim (1024); writes fp16 directly (GEMM operand).
// ---------------------------------------------------------------------------
__global__ __launch_bounds__(256)
void layernorm_half_kernel(const float* __restrict__ x, const float* __restrict__ g,
                           const float* __restrict__ b, __half* __restrict__ y)
{
    const long long row = blockIdx.x;
    const int tid = threadIdx.x;
    float4 v = ((const float4*)(x + row * HH))[tid];

    __shared__ float red[8];
    float s = v.x + v.y + v.z + v.w;
    #pragma unroll
    for (int o = 16; o; o >>= 1) s += __shfl_xor_sync(0xffffffffu, s, o);
    if ((tid & 31) == 0) red[tid >> 5] = s;
    __syncthreads();
    float mean = (red[0] + red[1] + red[2] + red[3] +
                  red[4] + red[5] + red[6] + red[7]) * (1.f / HH);
    __syncthreads();

    float dx = v.x - mean, dy = v.y - mean, dz = v.z - mean, dw = v.w - mean;
    float sq = dx * dx + dy * dy + dz * dz + dw * dw;
    #pragma unroll
    for (int o = 16; o; o >>= 1) sq += __shfl_xor_sync(0xffffffffu, sq, o);
    if ((tid & 31) == 0) red[tid >> 5] = sq;
    __syncthreads();
    float var = (red[0] + red[1] + red[2] + red[3] +
                 red[4] + red[5] + red[6] + red[7]) * (1.f / HH);
    float rstd = rsqrtf(var + 1e-5f);

    float4 g4 = ((const float4*)g)[tid];
    float4 b4 = ((const float4*)b)[tid];
    float y0 = dx * rstd * g4.x + b4.x;
    float y1 = dy * rstd * g4.y + b4.y;
    float y2 = dz * rstd * g4.z + b4.z;
    float y3 = dw * rstd * g4.w + b4.w;

    __half2* o = (__half2*)(y + row * HH + tid * 4);
    o[0] = __floats2half2_rn(y0, y1);
    o[1] = __floats2half2_rn(y2, y3);
}

// ---------------------------------------------------------------------------
// Host orchestration
// ---------------------------------------------------------------------------
extern "C" void kernel_launch(void* const* d_in, const int* in_sizes, int n_in,
                              void* d_out, int out_size)
{
    const float* input_ = (const float*)d_in[0];
    const float* enc    = (const float*)d_in[1];
    const float* Wq_s = (const float*)d_in[4];
    const float* Wk_s = (const float*)d_in[5];
    const float* Wv_s = (const float*)d_in[6];
    const float* Wo_s = (const float*)d_in[7];
    const float* Wq_c = (const float*)d_in[8];
    const float* Wk_c = (const float*)d_in[9];
    const float* Wv_c = (const float*)d_in[10];
    const float* Wo_c = (const float*)d_in[11];
    const float* w1   = (const float*)d_in[12];
    const float* b1   = (const float*)d_in[13];
    const float* w2   = (const float*)d_in[14];
    const float* b2   = (const float*)d_in[15];
    const float* g_mmha = (const float*)d_in[16];
    const float* b_mmha = (const float*)d_in[17];
    const float* g_mha  = (const float*)d_in[18];
    const float* b_mha  = (const float*)d_in[19];
    const float* g_ffn  = (const float*)d_in[20];
    const float* b_ffn  = (const float*)d_in[21];
    float* out = (float*)d_out;

    float *q, *k, *v, *x, *z;
    __half *a, *hid, *bw;
    cudaGetSymbolAddress((void**)&q,   ws_q);
    cudaGetSymbolAddress((void**)&k,   ws_k);
    cudaGetSymbolAddress((void**)&v,   ws_v);
    cudaGetSymbolAddress((void**)&x,   ws_x);
    cudaGetSymbolAddress((void**)&z,   ws_z);
    cudaGetSymbolAddress((void**)&a,   ws_a);
    cudaGetSymbolAddress((void**)&hid, ws_hid);
    cudaGetSymbolAddress((void**)&bw,  ws_b);

    cudaFuncSetAttribute(flash_tc_kernel,
                         cudaFuncAttributeMaxDynamicSharedMemorySize, FLASH_SMEM);
    cudaFuncSetAttribute(gemm_fp16_kernel,
                         cudaFuncAttributeMaxDynamicSharedMemorySize, GEMM_SMEM);

    auto tohalf = [&](const float* src, __half* dst, long long n) {
        tohalf_kernel<<<(int)(n / 1024), 256>>>(src, dst);
    };
    // C = A @ W^T ; fp16 operands; fp32 or fp16 output
    auto gemm = [&](const __half* pA, float* C, __half* Ch, int M, int N, int K,
                    const float* bias, const float* resid, int relu, int round_out) {
        dim3 grid(N / 128, M / 128, 1);
        gemm_fp16_kernel<<<grid, 256, GEMM_SMEM>>>(pA, bw, C, Ch, N, M, N, K,
                                                   bias, resid, N, relu, round_out);
    };
    auto flash = [&](const float* Q, const float* K, const float* V, __half* O,
                     int Tk, int causal) {
        dim3 grid(TT / FBQ, BB * NHH);
        flash_tc_kernel<<<grid, 256, FLASH_SMEM>>>(Q, K, V, O, Tk, causal);
    };

    const long long nW  = (long long)HH * HH;
    const long long nW1 = (long long)FF * HH;
    const long long nMH = (long long)MM * HH;

    // ---- self attention ----  (q,k,v: fp32, rna-tf32 rounded -> tf32 flash)
    layernorm_half_kernel<<<MM, 256>>>(input_, g_mmha, b_mmha, a);
    tohalf(Wq_s, bw, nW);  gemm(a, q, 0, MM, HH, HH, nullptr, nullptr, 0, 1);
    tohalf(Wk_s, bw, nW);  gemm(a, k, 0, MM, HH, HH, nullptr, nullptr, 0, 1);
    tohalf(Wv_s, bw, nW);  gemm(a, v, 0, MM, HH, HH, nullptr, nullptr, 0, 1);
    flash(q, k, v, a, TT, /*causal=*/1);                 // ctx (fp16) -> a
    tohalf(Wo_s, bw, nW);  gemm(a, x, 0, MM, HH, HH, nullptr, input_, 0, 0);

    // ---- cross attention ----
    layernorm_half_kernel<<<MM, 256>>>(x, g_mha, b_mha, a);
    tohalf(Wq_c, bw, nW);  gemm(a, q, 0, MM, HH, HH, nullptr, nullptr, 0, 1);
    tohalf(enc, a, nMH);                                 // enc (fp16) -> a
    tohalf(Wk_c, bw, nW);  gemm(a, k, 0, BB * TEE, HH, HH, nullptr, nullptr, 0, 1);
    tohalf(Wv_c, bw, nW);  gemm(a, v, 0, BB * TEE, HH, HH, nullptr, nullptr, 0, 1);
    flash(q, k, v, a, TEE, /*causal=*/0);
    tohalf(Wo_c, bw, nW);  gemm(a, z, 0, MM, HH, HH, nullptr, x, 0, 0);

    // ---- FFN ----
    layernorm_half_kernel<<<MM, 256>>>(z, g_ffn, b_ffn, a);
    tohalf(w1, bw, nW1);   gemm(a, 0, hid, MM, FF, HH, b1, nullptr, 1, 0);
    tohalf(w2, bw, nW1);   gemm(hid, out, 0, MM, HH, FF, b2, z, 0, 0);
}